// round 1
// baseline (speedup 1.0000x reference)
#include <cuda_runtime.h>
#include <cuda_bf16.h>
#include <math.h>

#define BATCH 2
#define NPTS 8192
#define NB (BATCH * NPTS)       // 16384
#define KNN 24
#define DM 128
#define PE_D 60
#define RROWS (NB * KNN)        // 393216

// ---------------- static device scratch (no allocations allowed) ----------------
__device__ float g_x[(size_t)NB * DM];          // 8 MB   : x = features@fc1+b
__device__ float g_sq[NB];                       //        : squared norms of xyz
__device__ int   g_idx[(size_t)NB * KNN];        // 1.5 MB : knn indices (batch-local)
__device__ float g_bufA[(size_t)RROWS * DM];     // 201 MB : h1 / attn_in / attn_pre
__device__ float g_bufB[(size_t)RROWS * DM];     // 201 MB : pos_enc
__device__ float g_res0[(size_t)NB * DM];        // 8 MB   : pre-fc2 result

// ---------------- kernel 1: x = features@fc1 + b, sqnorm ----------------
__global__ void k_fc1(const float* __restrict__ feat, const float* __restrict__ xyz,
                      const float* __restrict__ w, const float* __restrict__ b) {
    __shared__ float sf[8][32];
    int n0 = blockIdx.x * 8;
    int t = threadIdx.x;
    for (int e = t; e < 8 * 32; e += 128)
        sf[e / 32][e % 32] = feat[(size_t)(n0 + e / 32) * 32 + (e % 32)];
    __syncthreads();
    float acc[8];
#pragma unroll
    for (int r = 0; r < 8; ++r) acc[r] = 0.0f;
    int d = t;
    for (int c = 0; c < 32; ++c) {
        float wv = w[c * DM + d];
#pragma unroll
        for (int r = 0; r < 8; ++r) acc[r] = fmaf(sf[r][c], wv, acc[r]);
    }
    float bv = b[d];
#pragma unroll
    for (int r = 0; r < 8; ++r)
        g_x[(size_t)(n0 + r) * DM + d] = acc[r] + bv;
    if (t < 8) {
        int n = n0 + t;
        float x0 = xyz[(size_t)n * 3 + 0];
        float x1 = xyz[(size_t)n * 3 + 1];
        float x2 = xyz[(size_t)n * 3 + 2];
        g_sq[n] = __fadd_rn(__fadd_rn(__fmul_rn(x0, x0), __fmul_rn(x1, x1)), __fmul_rn(x2, x2));
    }
}

// ---------------- kernel 2: brute-force KNN (one thread per query) ----------------
__global__ void k_knn(const float* __restrict__ xyz) {
    const int TPB = 128;
    int q = blockIdx.x * TPB + threadIdx.x;       // 0..16383 (block within one batch)
    int b = q / NPTS;
    int base = b * NPTS;

    float qx = xyz[(size_t)q * 3 + 0];
    float qy = xyz[(size_t)q * 3 + 1];
    float qz = xyz[(size_t)q * 3 + 2];
    float qs = g_sq[q];

    float dist[KNN];
    int   nidx[KNN];
#pragma unroll
    for (int i = 0; i < KNN; ++i) { dist[i] = INFINITY; nidx[i] = 0; }

    __shared__ float4 tile[512];
    for (int t0 = 0; t0 < NPTS; t0 += 512) {
        __syncthreads();
        for (int i = threadIdx.x; i < 512; i += TPB) {
            int m = base + t0 + i;
            tile[i] = make_float4(xyz[(size_t)m * 3 + 0], xyz[(size_t)m * 3 + 1],
                                  xyz[(size_t)m * 3 + 2], g_sq[m]);
        }
        __syncthreads();
        for (int i = 0; i < 512; ++i) {
            float4 c = tile[i];
            float dot = __fadd_rn(__fadd_rn(__fmul_rn(qx, c.x), __fmul_rn(qy, c.y)),
                                  __fmul_rn(qz, c.z));
            float dd = __fsub_rn(__fadd_rn(qs, c.w), __fmul_rn(2.0f, dot));
            if (dd < dist[KNN - 1]) {
                int j = KNN - 1;
                while (j > 0 && dist[j - 1] > dd) {
                    dist[j] = dist[j - 1]; nidx[j] = nidx[j - 1]; --j;
                }
                dist[j] = dd; nidx[j] = t0 + i;
            }
        }
    }
#pragma unroll
    for (int k = 0; k < KNN; ++k) g_idx[(size_t)q * KNN + k] = nidx[k];
}

// ---------------- kernel 3: pe + h1 = relu(pe@d1 + b) ----------------
__global__ void k_pe(const float* __restrict__ xyz, const float* __restrict__ d1w,
                     const float* __restrict__ d1b) {
    int n = blockIdx.x;                 // global node
    int b = n / NPTS;
    int base = b * NPTS;
    int t = threadIdx.x;                // 128 threads

    __shared__ float w1[PE_D * DM];     // 30 KB
    __shared__ float pe[KNN][PE_D];     // 5.8 KB
    __shared__ float gk[KNN][3];
    __shared__ float omega[10];
    __shared__ int   sidx[KNN];
    __shared__ float q3[3];

    for (int e = t; e < PE_D * DM; e += 128) w1[e] = d1w[e];
    if (t < 10) omega[t] = 1.0f / powf(10000.0f, (float)t / 10.0f);
    if (t < KNN) sidx[t] = g_idx[(size_t)n * KNN + t];
    if (t < 3)   q3[t] = xyz[(size_t)n * 3 + t];
    __syncthreads();

    if (t < KNN * 3) {
        int k = t / 3, c = t % 3;
        gk[k][c] = q3[c] - xyz[(size_t)(base + sidx[k]) * 3 + c];
    }
    __syncthreads();

    for (int e = t; e < KNN * PE_D; e += 128) {
        int k = e / PE_D, j = e % PE_D;
        int c = j / 20, r = j % 20;
        float p = gk[k][c] * omega[r % 10];
        pe[k][j] = (r < 10) ? sinf(p) : cosf(p);
    }
    __syncthreads();

    int d = t;
    float acc[KNN];
#pragma unroll
    for (int k = 0; k < KNN; ++k) acc[k] = 0.0f;
    for (int j = 0; j < PE_D; ++j) {
        float wv = w1[j * DM + d];
#pragma unroll
        for (int k = 0; k < KNN; ++k) acc[k] = fmaf(pe[k][j], wv, acc[k]);
    }
    float bv = d1b[d];
#pragma unroll
    for (int k = 0; k < KNN; ++k)
        g_bufA[((size_t)n * KNN + k) * DM + d] = fmaxf(acc[k] + bv, 0.0f);
}

// ---------------- generic 128-wide GEMM: C = act(A@W + b) ----------------
// A: [rows,128], W: [128,128], tiles: BM=128, BN=128, BK=32; 256 threads, 8x8/thread
__global__ void k_gemm(const float* __restrict__ A, const float* __restrict__ W,
                       const float* __restrict__ bias, float* __restrict__ C, int act) {
    __shared__ float As[32 * 132];   // transposed: As[k][row], padded stride 132
    __shared__ float Ws[32 * 128];   // Ws[k][d]
    int r0 = blockIdx.x * 128;
    int tid = threadIdx.x;
    int tx = tid & 15, ty = tid >> 4;

    float acc[8][8];
#pragma unroll
    for (int i = 0; i < 8; ++i)
#pragma unroll
        for (int j = 0; j < 8; ++j) acc[i][j] = 0.0f;

    for (int kt = 0; kt < 128; kt += 32) {
        {
            int i0 = tid >> 3;
            int kk = (tid & 7) * 4;
#pragma unroll
            for (int u = 0; u < 4; ++u) {
                int i = i0 + u * 32;
                float4 v = *reinterpret_cast<const float4*>(&A[(size_t)(r0 + i) * 128 + kt + kk]);
                As[(kk + 0) * 132 + i] = v.x;
                As[(kk + 1) * 132 + i] = v.y;
                As[(kk + 2) * 132 + i] = v.z;
                As[(kk + 3) * 132 + i] = v.w;
            }
        }
        {
            int kk = tid >> 5;
            int d = (tid & 31) * 4;
#pragma unroll
            for (int u = 0; u < 4; ++u) {
                int k2 = kk + u * 8;
                *reinterpret_cast<float4*>(&Ws[k2 * 128 + d]) =
                    *reinterpret_cast<const float4*>(&W[(size_t)(kt + k2) * 128 + d]);
            }
        }
        __syncthreads();
#pragma unroll
        for (int kk = 0; kk < 32; ++kk) {
            float4 a0 = *reinterpret_cast<float4*>(&As[kk * 132 + ty * 8]);
            float4 a1 = *reinterpret_cast<float4*>(&As[kk * 132 + ty * 8 + 4]);
            float4 w0 = *reinterpret_cast<float4*>(&Ws[kk * 128 + tx * 8]);
            float4 w1 = *reinterpret_cast<float4*>(&Ws[kk * 128 + tx * 8 + 4]);
            float av[8] = {a0.x, a0.y, a0.z, a0.w, a1.x, a1.y, a1.z, a1.w};
            float wv[8] = {w0.x, w0.y, w0.z, w0.w, w1.x, w1.y, w1.z, w1.w};
#pragma unroll
            for (int i = 0; i < 8; ++i)
#pragma unroll
                for (int j = 0; j < 8; ++j)
                    acc[i][j] = fmaf(av[i], wv[j], acc[i][j]);
        }
        __syncthreads();
    }
#pragma unroll
    for (int i = 0; i < 8; ++i) {
        size_t r = (size_t)(r0 + ty * 8 + i);
#pragma unroll
        for (int j = 0; j < 8; ++j) {
            float v = acc[i][j] + bias[tx * 8 + j];
            if (act) v = fmaxf(v, 0.0f);
            C[r * 128 + tx * 8 + j] = v;
        }
    }
}

// ---------------- attn_in = x[n] - x[idx] + pos_enc (vectorized) ----------------
__global__ void k_attn_in() {
    size_t gid = (size_t)blockIdx.x * blockDim.x + threadIdx.x;   // over RROWS*32 float4
    if (gid >= (size_t)RROWS * 32) return;
    int c4 = (int)(gid & 31);
    size_t r = gid >> 5;
    int n = (int)(r / KNN);
    int b = n >> 13;
    int base = b << 13;
    int id = g_idx[r];
    const float4* xq = reinterpret_cast<const float4*>(&g_x[(size_t)n * DM]) + c4;
    const float4* xk = reinterpret_cast<const float4*>(&g_x[(size_t)(base + id) * DM]) + c4;
    const float4* pp = reinterpret_cast<const float4*>(&g_bufB[r * DM]) + c4;
    float4 a = *xq, bb = *xk, p = *pp;
    float4 o;
    o.x = (a.x - bb.x) + p.x;
    o.y = (a.y - bb.y) + p.y;
    o.z = (a.z - bb.z) + p.z;
    o.w = (a.w - bb.w) + p.w;
    *(reinterpret_cast<float4*>(&g_bufA[r * DM]) + c4) = o;
}

// ---------------- softmax over K + weighted sum ----------------
__global__ void k_softmax(float* __restrict__ attn_out) {
    int n = blockIdx.x;
    int d = threadIdx.x;                 // 128
    int b = n >> 13;
    int base = b << 13;
    const float inv = 0.088388347648318447f;   // 1/sqrt(128)

    __shared__ int sidx[KNN];
    if (d < KNN) sidx[d] = g_idx[(size_t)n * KNN + d];
    __syncthreads();

    size_t roff = (size_t)n * KNN * DM + d;
    float a[KNN];
#pragma unroll
    for (int k = 0; k < KNN; ++k) a[k] = g_bufA[roff + (size_t)k * DM] * inv;
    float m = a[0];
#pragma unroll
    for (int k = 1; k < KNN; ++k) m = fmaxf(m, a[k]);
    float s = 0.0f;
#pragma unroll
    for (int k = 0; k < KNN; ++k) { a[k] = expf(a[k] - m); s += a[k]; }
    float rs = 1.0f / s;

    float acc = 0.0f;
#pragma unroll
    for (int k = 0; k < KNN; ++k) {
        float at = a[k] * rs;
        attn_out[roff + (size_t)k * DM] = at;
        float vv = g_x[(size_t)(base + sidx[k]) * DM + d] + g_bufB[roff + (size_t)k * DM];
        acc = fmaf(at, vv, acc);
    }
    g_res0[(size_t)n * DM + d] = acc;
}

// ---------------- final: out = res0@fc2 + b + x ----------------
__global__ void k_final(const float* __restrict__ w, const float* __restrict__ b,
                        float* __restrict__ out_res) {
    __shared__ float s[8][DM];
    int n0 = blockIdx.x * 8;
    int t = threadIdx.x;
    for (int e = t; e < 8 * DM; e += 128)
        s[e >> 7][e & 127] = g_res0[(size_t)(n0 + (e >> 7)) * DM + (e & 127)];
    __syncthreads();
    float acc[8];
#pragma unroll
    for (int r = 0; r < 8; ++r) acc[r] = 0.0f;
    for (int c = 0; c < DM; ++c) {
        float wv = w[c * DM + t];
#pragma unroll
        for (int r = 0; r < 8; ++r) acc[r] = fmaf(s[r][c], wv, acc[r]);
    }
    float bv = b[t];
#pragma unroll
    for (int r = 0; r < 8; ++r)
        out_res[(size_t)(n0 + r) * DM + t] = (acc[r] + bv) + g_x[(size_t)(n0 + r) * DM + t];
}

// ---------------- launch ----------------
extern "C" void kernel_launch(void* const* d_in, const int* in_sizes, int n_in,
                              void* d_out, int out_size) {
    const float* features = (const float*)d_in[0];
    const float* xyz      = (const float*)d_in[1];
    const float* fc1_w    = (const float*)d_in[2];
    const float* fc1_b    = (const float*)d_in[3];
    const float* fc2_w    = (const float*)d_in[4];
    const float* fc2_b    = (const float*)d_in[5];
    const float* d1_w     = (const float*)d_in[6];
    const float* d1_b     = (const float*)d_in[7];
    const float* d2_w     = (const float*)d_in[8];
    const float* d2_b     = (const float*)d_in[9];
    const float* g1_w     = (const float*)d_in[10];
    const float* g1_b     = (const float*)d_in[11];
    const float* g2_w     = (const float*)d_in[12];
    const float* g2_b     = (const float*)d_in[13];

    float* out      = (float*)d_out;
    float* out_res  = out;                               // [2,8192,128]
    float* out_attn = out + (size_t)NB * DM;             // [2,8192,24,128]

    float *pA = nullptr, *pB = nullptr;
    cudaGetSymbolAddress((void**)&pA, g_bufA);
    cudaGetSymbolAddress((void**)&pB, g_bufB);

    // 1. x = features@fc1 + b ; sqnorms
    k_fc1<<<NB / 8, 128>>>(features, xyz, fc1_w, fc1_b);
    // 2. KNN
    k_knn<<<NB / 128, 128>>>(xyz);
    // 3. h1 = relu(pe@d1 + b) -> bufA
    k_pe<<<NB, 128>>>(xyz, d1_w, d1_b);
    // 4. pos_enc = bufA@d2 + b -> bufB
    k_gemm<<<RROWS / 128, 256>>>(pA, d2_w, d2_b, pB, 0);
    // 5. attn_in = x - gather(x) + pos_enc -> bufA
    {
        size_t tot = (size_t)RROWS * 32;
        k_attn_in<<<(unsigned)((tot + 255) / 256), 256>>>();
    }
    // 6. t = relu(attn_in@g1 + b) -> out_attn (temp)
    k_gemm<<<RROWS / 128, 256>>>(pA, g1_w, g1_b, out_attn, 1);
    // 7. attn_pre = t@g2 + b -> bufA
    k_gemm<<<RROWS / 128, 256>>>(out_attn, g2_w, g2_b, pA, 0);
    // 8. softmax + weighted sum: attn -> out_attn, res0
    k_softmax<<<NB, 128>>>(out_attn);
    // 9. res = res0@fc2 + b + x -> out_res
    k_final<<<NB / 8, 128>>>(fc2_w, fc2_b, out_res);
}